// round 3
// baseline (speedup 1.0000x reference)
#include <cuda_runtime.h>
#include <cuda_bf16.h>

// Problem constants: pred [8,16,512,512] f32, target [8,512,512] int32
#define N_IMG   8
#define N_CLS   16
#define HW      262144            // 512*512
#define NPIX    (N_IMG * HW)      // 2097152
#define CHW     (N_CLS * HW)
#define HW4     (HW / 4)          // 65536 float4 groups per channel-plane
#define BPI     128               // blocks per image in main kernel
#define MAIN_BLOCKS (N_IMG * BPI) // 1024
#define HIST_BLOCKS 256           // 256 blk * 256 thr * 8 int4 = NPIX/4 int4

// Scratch (__device__ globals; no cudaMalloc allowed)
__device__ unsigned int g_hpart[HIST_BLOCKS][N_CLS]; // per-block class counts
__device__ float        g_w[N_CLS];                  // class weights
__device__ unsigned int g_hctr;                      // hist completion counter
__device__ float        g_pnum[MAIN_BLOCKS];         // per-block num partials
__device__ float        g_pden[MAIN_BLOCKS];         // per-block den partials
__device__ unsigned int g_mctr;                      // main completion counter

// ---------------------------------------------------------------------------
// Kernel 1: per-class histogram of int32 targets. Nibble-packed counters
// flushed to 16 register accumulators every 8 pixels (capacity-safe).
// Plain-store block partials (no zeroing needed); last block computes the
// inverse-frequency weights and self-resets the counter.
// ---------------------------------------------------------------------------
__global__ __launch_bounds__(256) void dwce_hist(const int* __restrict__ target) {
    __shared__ unsigned int sh[N_CLS];
    __shared__ unsigned int s_last;
    int tid = threadIdx.x;
    if (tid < N_CLS) sh[tid] = 0u;
    __syncthreads();

    const int4* tv = (const int4*)target;       // NPIX/4 = 524288 int4 groups
    int base = blockIdx.x * 2048 + tid;         // 2048 int4 per block

    unsigned int acc[N_CLS];
#pragma unroll
    for (int c = 0; c < N_CLS; c++) acc[c] = 0u;

#pragma unroll
    for (int r = 0; r < 4; r++) {               // 4 rounds x 2 int4 = 8 int4/thread
        unsigned long long cnt = 0ull;
#pragma unroll
        for (int k = 0; k < 2; k++) {
            int4 a = tv[base + (r * 2 + k) * 256];
            cnt += (1ull << (a.x * 4)) + (1ull << (a.y * 4))
                 + (1ull << (a.z * 4)) + (1ull << (a.w * 4));
        }
#pragma unroll
        for (int c = 0; c < N_CLS; c++)
            acc[c] += (unsigned int)((cnt >> (4 * c)) & 0xFull);
    }

#pragma unroll
    for (int c = 0; c < N_CLS; c++) {
        unsigned int v = __reduce_add_sync(0xFFFFFFFFu, acc[c]);
        if ((tid & 31) == 0 && v) atomicAdd(&sh[c], v);
    }
    __syncthreads();
    if (tid < N_CLS) g_hpart[blockIdx.x][tid] = sh[tid];

    // last-block epilogue: reduce partials -> class weights
    __threadfence();
    if (tid == 0) s_last = atomicAdd(&g_hctr, 1u);
    __syncthreads();
    if (s_last == HIST_BLOCKS - 1) {
        __shared__ unsigned int red[256];
        unsigned int c = tid & 15;
        unsigned int s = 0;
        for (int b = (tid >> 4); b < HIST_BLOCKS; b += 16) s += g_hpart[b][c];
        red[tid] = s;
        __syncthreads();
        if (tid < N_CLS) {
            unsigned int tot = 0;
#pragma unroll
            for (int j = 0; j < 16; j++) tot += red[tid + j * 16];
            g_w[tid] = tot ? (1.0f / (16.0f * (float)tot)) : 0.0f;
        }
        if (tid == 0) g_hctr = 0u;  // deterministic reset for next replay
    }
}

// ---------------------------------------------------------------------------
// Kernel 2: main pass. Each thread handles 2 groups of 4 consecutive pixels.
// Per group: 1 int4 target load + 16 float4 channel loads (coalesced),
// softmax-lse, gather at target via unrolled compare-select, weighted
// accumulate. Block reduce -> plain-store partials; last block finalizes.
// ---------------------------------------------------------------------------
__global__ __launch_bounds__(256, 2) void dwce_main(const float* __restrict__ pred,
                                                    const int* __restrict__ target,
                                                    float* __restrict__ out) {
    __shared__ float sh_w[N_CLS];
    __shared__ float sn[8], sd[8];
    __shared__ unsigned int s_last;
    int tid = threadIdx.x;
    if (tid < N_CLS) sh_w[tid] = g_w[tid];
    __syncthreads();

    int img = blockIdx.x >> 7;      // / BPI
    int blk = blockIdx.x & (BPI - 1);
    const float4* pv = (const float4*)(pred + (size_t)img * CHW);
    const int4*   tv = (const int4*)(target + (size_t)img * HW);

    float num = 0.0f, den = 0.0f;

#pragma unroll
    for (int k = 0; k < 2; k++) {
        int g = k * 32768 + blk * 256 + tid;    // float4-group index within image
        int4 t4 = tv[g];
        int t0 = t4.x, t1 = t4.y, t2 = t4.z, t3 = t4.w;

        float4 v[N_CLS];
#pragma unroll
        for (int c = 0; c < N_CLS; c++) v[c] = pv[c * HW4 + g];

        float4 m = v[0];
#pragma unroll
        for (int c = 1; c < N_CLS; c++) {
            m.x = fmaxf(m.x, v[c].x); m.y = fmaxf(m.y, v[c].y);
            m.z = fmaxf(m.z, v[c].z); m.w = fmaxf(m.w, v[c].w);
        }

        float vt0 = 0.0f, vt1 = 0.0f, vt2 = 0.0f, vt3 = 0.0f;
        float4 s = make_float4(0.0f, 0.0f, 0.0f, 0.0f);
#pragma unroll
        for (int c = 0; c < N_CLS; c++) {
            if (c == t0) vt0 = v[c].x;
            if (c == t1) vt1 = v[c].y;
            if (c == t2) vt2 = v[c].z;
            if (c == t3) vt3 = v[c].w;
            s.x += __expf(v[c].x - m.x);
            s.y += __expf(v[c].y - m.y);
            s.z += __expf(v[c].z - m.z);
            s.w += __expf(v[c].w - m.w);
        }

        float l0 = m.x + __logf(s.x);
        float l1 = m.y + __logf(s.y);
        float l2 = m.z + __logf(s.z);
        float l3 = m.w + __logf(s.w);

        float w0 = sh_w[t0], w1 = sh_w[t1], w2 = sh_w[t2], w3 = sh_w[t3];
        num += w0 * (vt0 - l0);
        num += w1 * (vt1 - l1);
        num += w2 * (vt2 - l2);
        num += w3 * (vt3 - l3);
        den += (w0 + w1) + (w2 + w3);
    }

    // block reduce
#pragma unroll
    for (int o = 16; o > 0; o >>= 1) {
        num += __shfl_down_sync(0xFFFFFFFFu, num, o);
        den += __shfl_down_sync(0xFFFFFFFFu, den, o);
    }
    int w = tid >> 5, lane = tid & 31;
    if (lane == 0) { sn[w] = num; sd[w] = den; }
    __syncthreads();
    if (tid == 0) {
        float a = 0.0f, b = 0.0f;
#pragma unroll
        for (int i = 0; i < 8; i++) { a += sn[i]; b += sd[i]; }
        g_pnum[blockIdx.x] = a;
        g_pden[blockIdx.x] = b;
    }

    // last-block epilogue: per-image num/den -> loss
    __threadfence();
    if (tid == 0) s_last = atomicAdd(&g_mctr, 1u);
    __syncthreads();
    if (s_last == MAIN_BLOCKS - 1) {
        __shared__ float sr[8];
        float n = 0.0f, d = 0.0f;   // warp w reduces image w (128 partials)
#pragma unroll
        for (int j = 0; j < 4; j++) {
            int i = w * BPI + lane + j * 32;
            n += g_pnum[i]; d += g_pden[i];
        }
#pragma unroll
        for (int o = 16; o > 0; o >>= 1) {
            n += __shfl_down_sync(0xFFFFFFFFu, n, o);
            d += __shfl_down_sync(0xFFFFFFFFu, d, o);
        }
        if (lane == 0) sr[w] = n / d;
        __syncthreads();
        if (tid == 0) {
            float acc = 0.0f;
#pragma unroll
            for (int i = 0; i < N_IMG; i++) acc += sr[i];
            out[0] = -acc * (1.0f / (float)N_IMG);
            g_mctr = 0u;            // deterministic reset for next replay
        }
    }
}

// ---------------------------------------------------------------------------
extern "C" void kernel_launch(void* const* d_in, const int* in_sizes, int n_in,
                              void* d_out, int out_size) {
    const float* pred   = (const float*)d_in[0];
    const int*   target = (const int*)d_in[1];
    // d_in[2] (weights) is ignored by the reference module.
    float* out = (float*)d_out;

    dwce_hist<<<HIST_BLOCKS, 256>>>(target);
    dwce_main<<<MAIN_BLOCKS, 256>>>(pred, target, out);
}